// round 1
// baseline (speedup 1.0000x reference)
#include <cuda_runtime.h>
#include <cstddef>

// Problem constants
#define BB   2
#define SS   2048
#define DD   1024
#define HH   16
#define DK   64
#define MROWS (BB*SS)          // 4096

// Scratch (allocation-free rule: __device__ globals)
__device__ float g_q[MROWS*DD];
__device__ float g_k[MROWS*DD];
__device__ float g_v[MROWS*DD];
__device__ float g_att[MROWS*DD];

// ---------------------------------------------------------------------------
// SGEMM: C[M,N] = A[M,K] @ W[K,N] + bias,  128x128x8 tiles, 8x8 micro-tiles
// ---------------------------------------------------------------------------
#define GBM 128
#define GBN 128
#define GBK 8

__global__ __launch_bounds__(256) void sgemm_bias_kernel(
    const float* __restrict__ A, const float* __restrict__ W,
    const float* __restrict__ bias, float* __restrict__ C,
    int M, int N, int K)
{
    __shared__ float As[GBK][GBM];
    __shared__ float Bs[GBK][GBN];

    const int tid = threadIdx.x;
    const int tx = tid & 15;        // 0..15 -> N
    const int ty = tid >> 4;        // 0..15 -> M
    const int bx = blockIdx.x;      // N tile
    const int by = blockIdx.y;      // M tile

    float acc[8][8] = {};

    const int aRow = tid >> 1;           // 0..127
    const int aCol = (tid & 1) * 4;      // 0 or 4
    const int bRow = tid >> 5;           // 0..7
    const int bCol = (tid & 31) * 4;     // 0..124

    const float* Ap = A + (size_t)(by*GBM + aRow)*K + aCol;
    const float* Wp = W + (size_t)bRow*N + bx*GBN + bCol;

    for (int k0 = 0; k0 < K; k0 += GBK) {
        float4 a4 = *(const float4*)Ap;
        float4 b4 = *(const float4*)Wp;
        As[aCol+0][aRow] = a4.x;
        As[aCol+1][aRow] = a4.y;
        As[aCol+2][aRow] = a4.z;
        As[aCol+3][aRow] = a4.w;
        *(float4*)&Bs[bRow][bCol] = b4;
        __syncthreads();

        #pragma unroll
        for (int k = 0; k < GBK; k++) {
            float4 a0 = *(const float4*)&As[k][ty*8];
            float4 a1 = *(const float4*)&As[k][ty*8+4];
            float4 b0 = *(const float4*)&Bs[k][tx*8];
            float4 b1 = *(const float4*)&Bs[k][tx*8+4];
            float ra[8] = {a0.x,a0.y,a0.z,a0.w,a1.x,a1.y,a1.z,a1.w};
            float rb[8] = {b0.x,b0.y,b0.z,b0.w,b1.x,b1.y,b1.z,b1.w};
            #pragma unroll
            for (int i = 0; i < 8; i++)
                #pragma unroll
                for (int j = 0; j < 8; j++)
                    acc[i][j] += ra[i] * rb[j];
        }
        __syncthreads();
        Ap += GBK;
        Wp += (size_t)GBK * N;
    }

    #pragma unroll
    for (int i = 0; i < 8; i++) {
        const int row = by*GBM + ty*8 + i;
        #pragma unroll
        for (int j = 0; j < 8; j++) {
            const int col = bx*GBN + tx*8 + j;
            C[(size_t)row*N + col] = acc[i][j] + bias[col];
        }
    }
}

// ---------------------------------------------------------------------------
// Flash attention (causal), fp32. One CTA per (b, h, qtile of 64 rows).
// Streaming softmax; O accumulator 4x4 per thread in registers.
// ---------------------------------------------------------------------------
#define PST 65   // padded stride for Qs/Ks/Ps (column reads -> conflict-free)
#define VST 68   // padded stride for Vs (keeps LDS.128 16B-aligned)

// smem floats: 3*64*65 + 64*68 + 3*64
#define FLASH_SMEM_FLOATS (3*64*PST + 64*VST + 192)
#define FLASH_SMEM_BYTES  (FLASH_SMEM_FLOATS*4)

__global__ __launch_bounds__(256) void flash_attn_kernel(
    const float* __restrict__ q, const float* __restrict__ k,
    const float* __restrict__ v, float* __restrict__ o)
{
    extern __shared__ float sm[];
    float* Qs   = sm;
    float* Ks   = Qs + 64*PST;
    float* Ps   = Ks + 64*PST;
    float* Vs   = Ps + 64*PST;
    float* mrow = Vs + 64*VST;
    float* lrow = mrow + 64;
    float* frow = lrow + 64;

    const int tid = threadIdx.x;
    const int tx = tid & 15;
    const int ty = tid >> 4;
    const int qt = (int)gridDim.x - 1 - (int)blockIdx.x;  // longest work first
    const int bh = blockIdx.y;
    const int b = bh >> 4;
    const int h = bh & 15;
    const size_t base = (size_t)b * SS * DD + (size_t)h * DK;

    // Load Q tile [64][64]
    for (int i = tid; i < 64*16; i += 256) {
        const int r  = i >> 4;
        const int c4 = (i & 15) << 2;
        float4 val = *(const float4*)&q[base + (size_t)(qt*64 + r)*DD + c4];
        Qs[r*PST + c4 + 0] = val.x;
        Qs[r*PST + c4 + 1] = val.y;
        Qs[r*PST + c4 + 2] = val.z;
        Qs[r*PST + c4 + 3] = val.w;
    }
    if (tid < 64) { mrow[tid] = -3.0e38f; lrow[tid] = 0.0f; }
    float oacc[4][4] = {};
    __syncthreads();

    for (int kt = 0; kt <= qt; kt++) {
        // Load K and V tiles
        for (int i = tid; i < 64*16; i += 256) {
            const int r  = i >> 4;
            const int c4 = (i & 15) << 2;
            const size_t g = base + (size_t)(kt*64 + r)*DD + c4;
            float4 kk4 = *(const float4*)&k[g];
            Ks[r*PST + c4 + 0] = kk4.x;
            Ks[r*PST + c4 + 1] = kk4.y;
            Ks[r*PST + c4 + 2] = kk4.z;
            Ks[r*PST + c4 + 3] = kk4.w;
            float4 vv4 = *(const float4*)&v[g];
            *(float4*)&Vs[r*VST + c4] = vv4;
        }
        __syncthreads();

        // S = Q @ K^T (64x64), 4x4 per thread
        float sacc[4][4] = {};
        #pragma unroll 8
        for (int d = 0; d < 64; d++) {
            float ra[4], rb[4];
            #pragma unroll
            for (int i = 0; i < 4; i++) ra[i] = Qs[(ty*4+i)*PST + d];
            #pragma unroll
            for (int j = 0; j < 4; j++) rb[j] = Ks[(tx*4+j)*PST + d];
            #pragma unroll
            for (int i = 0; i < 4; i++)
                #pragma unroll
                for (int j = 0; j < 4; j++)
                    sacc[i][j] += ra[i] * rb[j];
        }
        const bool diag = (kt == qt);
        #pragma unroll
        for (int i = 0; i < 4; i++) {
            #pragma unroll
            for (int j = 0; j < 4; j++) {
                float s = sacc[i][j] * 0.125f;   // 1/sqrt(64)
                if (diag && (tx*4+j > ty*4+i)) s = -1.0e30f;
                Ps[(ty*4+i)*PST + tx*4+j] = s;
            }
        }
        __syncthreads();

        // Streaming softmax per row (threads 0..63)
        if (tid < 64) {
            const float mold = mrow[tid];
            float mx = mold;
            #pragma unroll 8
            for (int c = 0; c < 64; c++) mx = fmaxf(mx, Ps[tid*PST + c]);
            const float fac = __expf(mold - mx);
            float sum = 0.0f;
            #pragma unroll 8
            for (int c = 0; c < 64; c++) {
                const float p = __expf(Ps[tid*PST + c] - mx);
                Ps[tid*PST + c] = p;
                sum += p;
            }
            mrow[tid] = mx;
            lrow[tid] = lrow[tid] * fac + sum;
            frow[tid] = fac;
        }
        __syncthreads();

        // Rescale O and accumulate O += P @ V
        float f[4];
        #pragma unroll
        for (int i = 0; i < 4; i++) f[i] = frow[ty*4+i];
        #pragma unroll
        for (int i = 0; i < 4; i++)
            #pragma unroll
            for (int j = 0; j < 4; j++)
                oacc[i][j] *= f[i];

        #pragma unroll 8
        for (int kk = 0; kk < 64; kk++) {
            float rp[4];
            #pragma unroll
            for (int i = 0; i < 4; i++) rp[i] = Ps[(ty*4+i)*PST + kk];
            float4 rv = *(const float4*)&Vs[kk*VST + tx*4];
            #pragma unroll
            for (int i = 0; i < 4; i++) {
                oacc[i][0] += rp[i] * rv.x;
                oacc[i][1] += rp[i] * rv.y;
                oacc[i][2] += rp[i] * rv.z;
                oacc[i][3] += rp[i] * rv.w;
            }
        }
        __syncthreads();   // protect Ks/Vs/Ps before next iteration
    }

    // Epilogue: normalize and write
    float linv[4];
    #pragma unroll
    for (int i = 0; i < 4; i++) linv[i] = 1.0f / lrow[ty*4+i];
    #pragma unroll
    for (int i = 0; i < 4; i++) {
        const size_t g = base + (size_t)(qt*64 + ty*4 + i)*DD + tx*4;
        #pragma unroll
        for (int j = 0; j < 4; j++)
            o[g + j] = oacc[i][j] * linv[i];
    }
}

// ---------------------------------------------------------------------------
// Launch
// ---------------------------------------------------------------------------
extern "C" void kernel_launch(void* const* d_in, const int* in_sizes, int n_in,
                              void* d_out, int out_size)
{
    const float* Q   = (const float*)d_in[0];
    const float* K   = (const float*)d_in[1];
    const float* V   = (const float*)d_in[2];
    const float* W_q = (const float*)d_in[3];
    const float* b_q = (const float*)d_in[4];
    const float* W_k = (const float*)d_in[5];
    const float* b_k = (const float*)d_in[6];
    const float* W_v = (const float*)d_in[7];
    const float* b_v = (const float*)d_in[8];
    const float* W_o = (const float*)d_in[9];
    const float* b_o = (const float*)d_in[10];
    float* out = (float*)d_out;

    float *gq, *gk, *gv, *ga;
    cudaGetSymbolAddress((void**)&gq, g_q);
    cudaGetSymbolAddress((void**)&gk, g_k);
    cudaGetSymbolAddress((void**)&gv, g_v);
    cudaGetSymbolAddress((void**)&ga, g_att);

    cudaFuncSetAttribute(flash_attn_kernel,
                         cudaFuncAttributeMaxDynamicSharedMemorySize,
                         FLASH_SMEM_BYTES);

    dim3 gThreads(256);
    dim3 gGrid(DD/GBN, MROWS/GBM);   // (8, 32)

    sgemm_bias_kernel<<<gGrid, gThreads>>>(Q, W_q, b_q, gq, MROWS, DD, DD);
    sgemm_bias_kernel<<<gGrid, gThreads>>>(K, W_k, b_k, gk, MROWS, DD, DD);
    sgemm_bias_kernel<<<gGrid, gThreads>>>(V, W_v, b_v, gv, MROWS, DD, DD);

    dim3 fGrid(SS/64, BB*HH);        // (32, 32)
    flash_attn_kernel<<<fGrid, 256, FLASH_SMEM_BYTES>>>(gq, gk, gv, ga);

    sgemm_bias_kernel<<<gGrid, gThreads>>>(ga, W_o, b_o, out, MROWS, DD, DD);
}

// round 3
// speedup vs baseline: 1.6436x; 1.6436x over previous
#include <cuda_runtime.h>
#include <cuda_bf16.h>
#include <cstdint>
#include <cstddef>

// Problem constants
#define BB   2
#define SS   2048
#define DD   1024
#define HH   16
#define DK   64
#define MROWS (BB*SS)          // 4096

// ---------------------------------------------------------------------------
// Scratch (__device__ globals; allocation-free rule)
// ---------------------------------------------------------------------------
__device__ float g_q[MROWS*DD];
__device__ float g_k[MROWS*DD];
__device__ float g_v[MROWS*DD];
__device__ float g_att[MROWS*DD];
__device__ __nv_bfloat16 g_ah[MROWS*DD];   // activation hi  [4096][1024]
__device__ __nv_bfloat16 g_al[MROWS*DD];   // activation lo
__device__ __nv_bfloat16 g_bh[DD*DD];      // W^T hi [n][k]
__device__ __nv_bfloat16 g_bl[DD*DD];      // W^T lo

// ---------------------------------------------------------------------------
// PTX helpers (base sm_103-safe: cp.async, ldmatrix, mma.sync only)
// ---------------------------------------------------------------------------
__device__ __forceinline__ uint32_t smem_u32(const void* p) {
    return (uint32_t)__cvta_generic_to_shared(p);
}

__device__ __forceinline__ void cpa16(uint32_t dst, const void* src) {
    asm volatile("cp.async.cg.shared.global [%0], [%1], 16;" :: "r"(dst), "l"(src) : "memory");
}
#define CP_COMMIT() asm volatile("cp.async.commit_group;" ::: "memory")
#define CP_WAIT1()  asm volatile("cp.async.wait_group 1;" ::: "memory")

__device__ __forceinline__ void ldsm_x4(uint32_t& r0, uint32_t& r1, uint32_t& r2, uint32_t& r3,
                                        uint32_t addr) {
    asm volatile("ldmatrix.sync.aligned.m8n8.x4.shared.b16 {%0,%1,%2,%3}, [%4];"
                 : "=r"(r0), "=r"(r1), "=r"(r2), "=r"(r3) : "r"(addr));
}

__device__ __forceinline__ void mma16816(float* d, const uint32_t* a, const uint32_t* b) {
    asm volatile("mma.sync.aligned.m16n8k16.row.col.f32.bf16.bf16.f32 "
                 "{%0,%1,%2,%3}, {%4,%5,%6,%7}, {%8,%9}, {%0,%1,%2,%3};"
                 : "+f"(d[0]), "+f"(d[1]), "+f"(d[2]), "+f"(d[3])
                 : "r"(a[0]), "r"(a[1]), "r"(a[2]), "r"(a[3]), "r"(b[0]), "r"(b[1]));
}

// ---------------------------------------------------------------------------
// Conversion kernels
// ---------------------------------------------------------------------------
__global__ __launch_bounds__(256) void conv_act(const float* __restrict__ A,
                                                __nv_bfloat16* __restrict__ H,
                                                __nv_bfloat16* __restrict__ L)
{
    const size_t idx = ((size_t)blockIdx.x * 256 + threadIdx.x) * 8;
    float4 x0 = *(const float4*)(A + idx);
    float4 x1 = *(const float4*)(A + idx + 4);
    float x[8] = {x0.x,x0.y,x0.z,x0.w,x1.x,x1.y,x1.z,x1.w};
    alignas(16) __nv_bfloat16 h8[8];
    alignas(16) __nv_bfloat16 l8[8];
    #pragma unroll
    for (int j = 0; j < 8; j++) {
        __nv_bfloat16 hi = __float2bfloat16(x[j]);
        h8[j] = hi;
        l8[j] = __float2bfloat16(x[j] - __bfloat162float(hi));
    }
    *(uint4*)(H + idx) = *(const uint4*)h8;
    *(uint4*)(L + idx) = *(const uint4*)l8;
}

// W[k][n] fp32 -> Bt[n][k] bf16 hi/lo. 64x64 transpose tiles.
__global__ __launch_bounds__(256) void conv_w(const float* __restrict__ W,
                                              __nv_bfloat16* __restrict__ H,
                                              __nv_bfloat16* __restrict__ L)
{
    __shared__ float t[64][65];
    const int c  = blockIdx.x;   // k block
    const int nj = blockIdx.y;   // n block

    #pragma unroll
    for (int it = 0; it < 4; it++) {
        const int idx = threadIdx.x + it*256;
        const int kr = idx >> 4;
        const int nc4 = (idx & 15)*4;
        float4 v = *(const float4*)&W[(size_t)(c*64 + kr)*1024 + nj*64 + nc4];
        t[kr][nc4+0] = v.x; t[kr][nc4+1] = v.y; t[kr][nc4+2] = v.z; t[kr][nc4+3] = v.w;
    }
    __syncthreads();

    #pragma unroll
    for (int it = 0; it < 2; it++) {
        const int item = threadIdx.x + it*256;   // 0..511
        const int r = item >> 3;                 // local n
        const int g = item & 7;                  // k octet
        alignas(16) __nv_bfloat16 h8[8];
        alignas(16) __nv_bfloat16 l8[8];
        #pragma unroll
        for (int j = 0; j < 8; j++) {
            float x = t[g*8 + j][r];
            __nv_bfloat16 hi = __float2bfloat16(x);
            h8[j] = hi;
            l8[j] = __float2bfloat16(x - __bfloat162float(hi));
        }
        const size_t off = (size_t)(nj*64 + r)*1024 + c*64 + g*8;
        *(uint4*)(H + off) = *(const uint4*)h8;
        *(uint4*)(L + off) = *(const uint4*)l8;
    }
}

// ---------------------------------------------------------------------------
// mma.sync bf16 GEMM: C[4096,1024] = A @ W + bias (B given as W^T [n][k])
// Split-bf16 x3: Ah*Bh + Ah*Bl + Al*Bh.
// CTA tile 256(M) x 128(N) x 32(K); 512 threads (16 warps, 4Mx4N).
// 2-stage cp.async pipeline. Smem rows padded to 40 bf16 (80 B).
// ---------------------------------------------------------------------------
#define GBM 256
#define GBN 128
#define GBK 32
#define GSTRIDE 40                         // bf16 elements per smem row
#define G_A_BYTES (GBM*GSTRIDE*2)          // 20480
#define G_B_BYTES (GBN*GSTRIDE*2)          // 10240
#define G_STAGE   (2*G_A_BYTES + 2*G_B_BYTES)   // 61440
#define G_SMEM    (2*G_STAGE)              // 122880

// stage s offsets
#define OFF_AH(s) ((s)*G_STAGE)
#define OFF_AL(s) ((s)*G_STAGE + G_A_BYTES)
#define OFF_BH(s) ((s)*G_STAGE + 2*G_A_BYTES)
#define OFF_BL(s) ((s)*G_STAGE + 2*G_A_BYTES + G_B_BYTES)

__device__ __forceinline__ void g_load_stage(
    uint32_t sb, int s, int k0, int mbase, int nbase,
    const __nv_bfloat16* Ah, const __nv_bfloat16* Al,
    const __nv_bfloat16* Bh, const __nv_bfloat16* Bl, int tid)
{
    // A: 256 rows x 4 octets = 1024 chunks; 2 per thread
    #pragma unroll
    for (int i = 0; i < 2; i++) {
        const int c = tid + i*512;
        const int row = c >> 2;
        const int kc  = (c & 3) * 8;
        const size_t g = (size_t)(mbase + row)*1024 + k0 + kc;
        const uint32_t d = sb + row*80 + kc*2;
        cpa16(d + OFF_AH(s), Ah + g);
        cpa16(d + OFF_AL(s), Al + g);
    }
    // B: 128 rows x 4 octets = 512 chunks; 1 per thread
    {
        const int row = tid >> 2;
        const int kc  = (tid & 3) * 8;
        const size_t g = (size_t)(nbase + row)*1024 + k0 + kc;
        const uint32_t d = sb + row*80 + kc*2;
        cpa16(d + OFF_BH(s), Bh + g);
        cpa16(d + OFF_BL(s), Bl + g);
    }
}

__global__ __launch_bounds__(512, 1) void gemm_mma(
    const __nv_bfloat16* __restrict__ Ah, const __nv_bfloat16* __restrict__ Al,
    const __nv_bfloat16* __restrict__ Bh, const __nv_bfloat16* __restrict__ Bl,
    const float* __restrict__ bias, float* __restrict__ C)
{
    extern __shared__ char smem[];
    const uint32_t sb = smem_u32(smem);
    const int tid = threadIdx.x;
    const int wid = tid >> 5;
    const int lid = tid & 31;
    const int warpM = (wid >> 2) * 64;      // 0,64,128,192
    const int warpN = (wid & 3) * 32;       // 0,32,64,96
    const int mbase = blockIdx.y * GBM;
    const int nbase = blockIdx.x * GBN;

    float acc[4][4][4];
    #pragma unroll
    for (int m = 0; m < 4; m++)
        #pragma unroll
        for (int n = 0; n < 4; n++)
            #pragma unroll
            for (int r = 0; r < 4; r++) acc[m][n][r] = 0.0f;

    // per-thread ldmatrix address components
    const int aRow  = warpM + (lid & 15);          // + m*16
    const int aKoff = (lid >> 4) * 8;              // 0/8
    const int bRow  = warpN + (lid & 7) + (lid >> 4)*8;   // + p*16
    const int bKoff = ((lid >> 3) & 1) * 8;

    g_load_stage(sb, 0, 0, mbase, nbase, Ah, Al, Bh, Bl, tid);
    CP_COMMIT();
    g_load_stage(sb, 1, GBK, mbase, nbase, Ah, Al, Bh, Bl, tid);
    CP_COMMIT();

    for (int it = 0; it < 32; it++) {
        const int s = it & 1;
        CP_WAIT1();
        __syncthreads();

        const uint32_t aBase = sb + OFF_AH(s) + aRow*80 + aKoff*2;
        const uint32_t alBase= sb + OFF_AL(s) + aRow*80 + aKoff*2;
        const uint32_t bBase = sb + OFF_BH(s) + bRow*80 + bKoff*2;
        const uint32_t blBase= sb + OFF_BL(s) + bRow*80 + bKoff*2;

        #pragma unroll
        for (int kk = 0; kk < 2; kk++) {        // two k16 steps per stage
            const uint32_t kb = kk * 32;        // 16 bf16 = 32 bytes
            uint32_t af[4][4], bh2[4][2], bl2[4][2];
            // B hi/lo: 2 ldmatrix.x4 each cover 2 n-tiles
            #pragma unroll
            for (int p = 0; p < 2; p++) {
                uint32_t r0,r1,r2,r3;
                ldsm_x4(r0,r1,r2,r3, bBase + p*16*80 + kb);
                bh2[p*2+0][0]=r0; bh2[p*2+0][1]=r1; bh2[p*2+1][0]=r2; bh2[p*2+1][1]=r3;
                ldsm_x4(r0,r1,r2,r3, blBase + p*16*80 + kb);
                bl2[p*2+0][0]=r0; bl2[p*2+0][1]=r1; bl2[p*2+1][0]=r2; bl2[p*2+1][1]=r3;
            }
            // A hi
            #pragma unroll
            for (int m = 0; m < 4; m++)
                ldsm_x4(af[m][0], af[m][1], af[m][2], af[m][3], aBase + m*16*80 + kb);
            #pragma unroll
            for (int m = 0; m < 4; m++)
                #pragma unroll
                for (int n = 0; n < 4; n++) {
                    mma16816(acc[m][n], af[m], bh2[n]);
                    mma16816(acc[m][n], af[m], bl2[n]);
                }
            // A lo reuses af regs
            #pragma unroll
            for (int m = 0; m < 4; m++)
                ldsm_x4(af[m][0], af[m][1], af[m][2], af[m][3], alBase + m*16*80 + kb);
            #pragma unroll
            for (int m = 0; m < 4; m++)
                #pragma unroll
                for (int n = 0; n < 4; n++)
                    mma16816(acc[m][n], af[m], bh2[n]);
        }
        __syncthreads();
        if (it + 2 < 32)
            g_load_stage(sb, s, (it + 2)*GBK, mbase, nbase, Ah, Al, Bh, Bl, tid);
        CP_COMMIT();   // unconditional: keeps wait_group accounting uniform
    }

    // Epilogue
    const int r0base = mbase + warpM + (lid >> 2);
    const int cbase  = nbase + warpN + (lid & 3)*2;
    #pragma unroll
    for (int m = 0; m < 4; m++) {
        #pragma unroll
        for (int n = 0; n < 4; n++) {
            const int cc = cbase + n*8;
            const float2 bi = *(const float2*)&bias[cc];
            const int ra = r0base + m*16;
            float2 o0 = { acc[m][n][0] + bi.x, acc[m][n][1] + bi.y };
            float2 o1 = { acc[m][n][2] + bi.x, acc[m][n][3] + bi.y };
            *(float2*)&C[(size_t)ra*1024 + cc] = o0;
            *(float2*)&C[(size_t)(ra + 8)*1024 + cc] = o1;
        }
    }
}

// ---------------------------------------------------------------------------
// Flash attention (causal), fp32, shuffle-based streaming softmax.
// ---------------------------------------------------------------------------
#define PST 65
#define VST 68
#define FLASH_SMEM_FLOATS (3*64*PST + 64*VST + 128)
#define FLASH_SMEM_BYTES  (FLASH_SMEM_FLOATS*4)

__global__ __launch_bounds__(256) void flash_attn_kernel(
    const float* __restrict__ q, const float* __restrict__ k,
    const float* __restrict__ v, float* __restrict__ o)
{
    extern __shared__ float sm[];
    float* Qs   = sm;
    float* Ks   = Qs + 64*PST;
    float* Ps   = Ks + 64*PST;
    float* Vs   = Ps + 64*PST;
    float* mrow = Vs + 64*VST;
    float* lrow = mrow + 64;

    const int tid = threadIdx.x;
    const int tx = tid & 15;
    const int ty = tid >> 4;
    const int qt = (int)gridDim.x - 1 - (int)blockIdx.x;
    const int bh = blockIdx.y;
    const int b = bh >> 4;
    const int h = bh & 15;
    const size_t base = (size_t)b * SS * DD + (size_t)h * DK;

    for (int i = tid; i < 64*16; i += 256) {
        const int r  = i >> 4;
        const int c4 = (i & 15) << 2;
        float4 val = *(const float4*)&q[base + (size_t)(qt*64 + r)*DD + c4];
        Qs[r*PST + c4 + 0] = val.x;
        Qs[r*PST + c4 + 1] = val.y;
        Qs[r*PST + c4 + 2] = val.z;
        Qs[r*PST + c4 + 3] = val.w;
    }
    if (tid < 64) { mrow[tid] = -3.0e38f; lrow[tid] = 0.0f; }
    float oacc[4][4] = {};
    __syncthreads();

    for (int kt = 0; kt <= qt; kt++) {
        for (int i = tid; i < 64*16; i += 256) {
            const int r  = i >> 4;
            const int c4 = (i & 15) << 2;
            const size_t g = base + (size_t)(kt*64 + r)*DD + c4;
            float4 kk4 = *(const float4*)&k[g];
            Ks[r*PST + c4 + 0] = kk4.x;
            Ks[r*PST + c4 + 1] = kk4.y;
            Ks[r*PST + c4 + 2] = kk4.z;
            Ks[r*PST + c4 + 3] = kk4.w;
            float4 vv4 = *(const float4*)&v[g];
            *(float4*)&Vs[r*VST + c4] = vv4;
        }
        __syncthreads();

        float sacc[4][4] = {};
        #pragma unroll 8
        for (int d = 0; d < 64; d++) {
            float ra[4], rb[4];
            #pragma unroll
            for (int i = 0; i < 4; i++) ra[i] = Qs[(ty*4+i)*PST + d];
            #pragma unroll
            for (int j = 0; j < 4; j++) rb[j] = Ks[(tx*4+j)*PST + d];
            #pragma unroll
            for (int i = 0; i < 4; i++)
                #pragma unroll
                for (int j = 0; j < 4; j++)
                    sacc[i][j] += ra[i] * rb[j];
        }
        const bool diag = (kt == qt);
        #pragma unroll
        for (int i = 0; i < 4; i++)
            #pragma unroll
            for (int j = 0; j < 4; j++) {
                float s = sacc[i][j] * 0.125f;
                if (diag && (tx*4+j > ty*4+i)) s = -1.0e30f;
                sacc[i][j] = s;
            }

        float mold[4], mnew[4], fac4[4], rsum[4];
        #pragma unroll
        for (int i = 0; i < 4; i++) {
            float m = fmaxf(fmaxf(sacc[i][0], sacc[i][1]), fmaxf(sacc[i][2], sacc[i][3]));
            #pragma unroll
            for (int d = 1; d < 16; d <<= 1)
                m = fmaxf(m, __shfl_xor_sync(0xffffffffu, m, d, 16));
            mold[i] = mrow[ty*4+i];
            mnew[i] = fmaxf(m, mold[i]);
            fac4[i] = __expf(mold[i] - mnew[i]);
            rsum[i] = 0.0f;
        }
        #pragma unroll
        for (int i = 0; i < 4; i++) {
            #pragma unroll
            for (int j = 0; j < 4; j++) {
                float p = __expf(sacc[i][j] - mnew[i]);
                Ps[(ty*4+i)*PST + tx*4+j] = p;
                rsum[i] += p;
            }
        }
        #pragma unroll
        for (int i = 0; i < 4; i++) {
            #pragma unroll
            for (int d = 1; d < 16; d <<= 1)
                rsum[i] += __shfl_xor_sync(0xffffffffu, rsum[i], d, 16);
        }
        if (tx == 0) {
            #pragma unroll
            for (int i = 0; i < 4; i++) {
                mrow[ty*4+i] = mnew[i];
                lrow[ty*4+i] = lrow[ty*4+i]*fac4[i] + rsum[i];
            }
        }
        __syncwarp();

        #pragma unroll
        for (int i = 0; i < 4; i++)
            #pragma unroll
            for (int j = 0; j < 4; j++)
                oacc[i][j] *= fac4[i];

        #pragma unroll 8
        for (int kk = 0; kk < 64; kk++) {
            float rp[4];
            #pragma unroll
            for (int i = 0; i < 4; i++) rp[i] = Ps[(ty*4+i)*PST + kk];
            float4 rv = *(const float4*)&Vs[kk*VST + tx*4];
            #pragma unroll
            for (int i = 0; i < 4; i++) {
                oacc[i][0] += rp[i] * rv.x;
                oacc[i][1] += rp[i] * rv.y;
                oacc[i][2] += rp[i] * rv.z;
                oacc[i][3] += rp[i] * rv.w;
            }
        }
        __syncthreads();
    }

    float linv[4];
    #pragma unroll
    for (int i = 0; i < 4; i++) linv[i] = 1.0f / lrow[ty*4+i];
    #pragma unroll
    for (int i = 0; i < 4; i++) {
        const size_t g = base + (size_t)(qt*64 + ty*4 + i)*DD + tx*4;
        #pragma unroll
        for (int j = 0; j < 4; j++)
            o[g + j] = oacc[i][j] * linv[i];
    }
}

// ---------------------------------------------------------------------------
// Launch
// ---------------------------------------------------------------------------
extern "C" void kernel_launch(void* const* d_in, const int* in_sizes, int n_in,
                              void* d_out, int out_size)
{
    const float* Q   = (const float*)d_in[0];
    const float* K   = (const float*)d_in[1];
    const float* V   = (const float*)d_in[2];
    const float* W_q = (const float*)d_in[3];
    const float* b_q = (const float*)d_in[4];
    const float* W_k = (const float*)d_in[5];
    const float* b_k = (const float*)d_in[6];
    const float* W_v = (const float*)d_in[7];
    const float* b_v = (const float*)d_in[8];
    const float* W_o = (const float*)d_in[9];
    const float* b_o = (const float*)d_in[10];
    float* out = (float*)d_out;

    float *gq, *gk, *gv, *ga;
    __nv_bfloat16 *ah, *al, *bh, *bl;
    cudaGetSymbolAddress((void**)&gq, g_q);
    cudaGetSymbolAddress((void**)&gk, g_k);
    cudaGetSymbolAddress((void**)&gv, g_v);
    cudaGetSymbolAddress((void**)&ga, g_att);
    cudaGetSymbolAddress((void**)&ah, g_ah);
    cudaGetSymbolAddress((void**)&al, g_al);
    cudaGetSymbolAddress((void**)&bh, g_bh);
    cudaGetSymbolAddress((void**)&bl, g_bl);

    cudaFuncSetAttribute(gemm_mma, cudaFuncAttributeMaxDynamicSharedMemorySize, G_SMEM);
    cudaFuncSetAttribute(flash_attn_kernel, cudaFuncAttributeMaxDynamicSharedMemorySize,
                         FLASH_SMEM_BYTES);

    const int caGrid = (MROWS*DD) / (256*8);   // 2048
    dim3 cwGrid(16, 16);
    dim3 gGrid(DD/GBN, MROWS/GBM);             // (8, 16) = 128 CTAs

    conv_act<<<caGrid, 256>>>(Q, ah, al);
    conv_w  <<<cwGrid, 256>>>(W_q, bh, bl);
    gemm_mma<<<gGrid, 512, G_SMEM>>>(ah, al, bh, bl, b_q, gq);

    conv_act<<<caGrid, 256>>>(K, ah, al);
    conv_w  <<<cwGrid, 256>>>(W_k, bh, bl);
    gemm_mma<<<gGrid, 512, G_SMEM>>>(ah, al, bh, bl, b_k, gk);

    conv_act<<<caGrid, 256>>>(V, ah, al);
    conv_w  <<<cwGrid, 256>>>(W_v, bh, bl);
    gemm_mma<<<gGrid, 512, G_SMEM>>>(ah, al, bh, bl, b_v, gv);

    dim3 fGrid(SS/64, BB*HH);
    flash_attn_kernel<<<fGrid, 256, FLASH_SMEM_BYTES>>>(gq, gk, gv, ga);

    conv_act<<<caGrid, 256>>>(ga, ah, al);
    conv_w  <<<cwGrid, 256>>>(W_o, bh, bl);
    gemm_mma<<<gGrid, 512, G_SMEM>>>(ah, al, bh, bl, b_o, out);
}

// round 4
// speedup vs baseline: 3.1076x; 1.8908x over previous
#include <cuda_runtime.h>
#include <cuda_bf16.h>
#include <cstdint>
#include <cstddef>

// Problem constants
#define BB   2
#define SS   2048
#define DD   1024
#define HH   16
#define DK   64
#define MROWS (BB*SS)          // 4096

// ---------------------------------------------------------------------------
// Scratch (__device__ globals; allocation-free rule)
// ---------------------------------------------------------------------------
__device__ __nv_bfloat16 g_xh[MROWS*DD];   // activation hi (GEMM input)
__device__ __nv_bfloat16 g_xl[MROWS*DD];   // activation lo
__device__ __nv_bfloat16 g_qh[MROWS*DD];
__device__ __nv_bfloat16 g_ql[MROWS*DD];
__device__ __nv_bfloat16 g_kh[MROWS*DD];
__device__ __nv_bfloat16 g_kl[MROWS*DD];
__device__ __nv_bfloat16 g_vh[MROWS*DD];
__device__ __nv_bfloat16 g_vl[MROWS*DD];
__device__ __nv_bfloat16 g_oh[MROWS*DD];   // attention out hi
__device__ __nv_bfloat16 g_ol[MROWS*DD];   // attention out lo
__device__ __nv_bfloat16 g_bh[DD*DD];      // W^T hi [n][k]
__device__ __nv_bfloat16 g_bl[DD*DD];      // W^T lo

// ---------------------------------------------------------------------------
// PTX helpers (base sm_103-safe: cp.async, ldmatrix, mma.sync only)
// ---------------------------------------------------------------------------
__device__ __forceinline__ uint32_t smem_u32(const void* p) {
    return (uint32_t)__cvta_generic_to_shared(p);
}

__device__ __forceinline__ void cpa16(uint32_t dst, const void* src) {
    asm volatile("cp.async.cg.shared.global [%0], [%1], 16;" :: "r"(dst), "l"(src) : "memory");
}
#define CP_COMMIT() asm volatile("cp.async.commit_group;" ::: "memory")
#define CP_WAIT1()  asm volatile("cp.async.wait_group 1;" ::: "memory")

__device__ __forceinline__ void ldsm_x4(uint32_t& r0, uint32_t& r1, uint32_t& r2, uint32_t& r3,
                                        uint32_t addr) {
    asm volatile("ldmatrix.sync.aligned.m8n8.x4.shared.b16 {%0,%1,%2,%3}, [%4];"
                 : "=r"(r0), "=r"(r1), "=r"(r2), "=r"(r3) : "r"(addr));
}
__device__ __forceinline__ void ldsm_x4t(uint32_t& r0, uint32_t& r1, uint32_t& r2, uint32_t& r3,
                                         uint32_t addr) {
    asm volatile("ldmatrix.sync.aligned.m8n8.x4.trans.shared.b16 {%0,%1,%2,%3}, [%4];"
                 : "=r"(r0), "=r"(r1), "=r"(r2), "=r"(r3) : "r"(addr));
}

__device__ __forceinline__ void mma16816(float* d, const uint32_t* a, uint32_t b0, uint32_t b1) {
    asm volatile("mma.sync.aligned.m16n8k16.row.col.f32.bf16.bf16.f32 "
                 "{%0,%1,%2,%3}, {%4,%5,%6,%7}, {%8,%9}, {%0,%1,%2,%3};"
                 : "+f"(d[0]), "+f"(d[1]), "+f"(d[2]), "+f"(d[3])
                 : "r"(a[0]), "r"(a[1]), "r"(a[2]), "r"(a[3]), "r"(b0), "r"(b1));
}

__device__ __forceinline__ uint32_t packbf(float lo, float hi) {
    uint32_t r;
    asm("cvt.rn.bf16x2.f32 %0, %1, %2;" : "=r"(r) : "f"(hi), "f"(lo));
    return r;
}

// ---------------------------------------------------------------------------
// Conversion kernels
// ---------------------------------------------------------------------------
__global__ __launch_bounds__(256) void conv_act(const float* __restrict__ A,
                                                __nv_bfloat16* __restrict__ H,
                                                __nv_bfloat16* __restrict__ L)
{
    const size_t idx = ((size_t)blockIdx.x * 256 + threadIdx.x) * 8;
    float4 x0 = *(const float4*)(A + idx);
    float4 x1 = *(const float4*)(A + idx + 4);
    float x[8] = {x0.x,x0.y,x0.z,x0.w,x1.x,x1.y,x1.z,x1.w};
    alignas(16) __nv_bfloat16 h8[8];
    alignas(16) __nv_bfloat16 l8[8];
    #pragma unroll
    for (int j = 0; j < 8; j++) {
        __nv_bfloat16 hi = __float2bfloat16(x[j]);
        h8[j] = hi;
        l8[j] = __float2bfloat16(x[j] - __bfloat162float(hi));
    }
    *(uint4*)(H + idx) = *(const uint4*)h8;
    *(uint4*)(L + idx) = *(const uint4*)l8;
}

// W[k][n] fp32 -> Bt[n][k] bf16 hi/lo. 64x64 transpose tiles.
__global__ __launch_bounds__(256) void conv_w(const float* __restrict__ W,
                                              __nv_bfloat16* __restrict__ H,
                                              __nv_bfloat16* __restrict__ L)
{
    __shared__ float t[64][65];
    const int c  = blockIdx.x;   // k block
    const int nj = blockIdx.y;   // n block

    #pragma unroll
    for (int it = 0; it < 4; it++) {
        const int idx = threadIdx.x + it*256;
        const int kr = idx >> 4;
        const int nc4 = (idx & 15)*4;
        float4 v = *(const float4*)&W[(size_t)(c*64 + kr)*1024 + nj*64 + nc4];
        t[kr][nc4+0] = v.x; t[kr][nc4+1] = v.y; t[kr][nc4+2] = v.z; t[kr][nc4+3] = v.w;
    }
    __syncthreads();

    #pragma unroll
    for (int it = 0; it < 2; it++) {
        const int item = threadIdx.x + it*256;   // 0..511
        const int r = item >> 3;                 // local n
        const int g = item & 7;                  // k octet
        alignas(16) __nv_bfloat16 h8[8];
        alignas(16) __nv_bfloat16 l8[8];
        #pragma unroll
        for (int j = 0; j < 8; j++) {
            float x = t[g*8 + j][r];
            __nv_bfloat16 hi = __float2bfloat16(x);
            h8[j] = hi;
            l8[j] = __float2bfloat16(x - __bfloat162float(hi));
        }
        const size_t off = (size_t)(nj*64 + r)*1024 + c*64 + g*8;
        *(uint4*)(H + off) = *(const uint4*)h8;
        *(uint4*)(L + off) = *(const uint4*)l8;
    }
}

// ---------------------------------------------------------------------------
// mma.sync bf16 GEMM: C = A @ W + bias. Split-bf16 x3.
// CTA 256x128x32, 512 threads, 2-stage cp.async. Output fp32 OR bf16 hi/lo.
// ---------------------------------------------------------------------------
#define GBM 256
#define GBN 128
#define GBK 32
#define G_A_BYTES (GBM*40*2)
#define G_B_BYTES (GBN*40*2)
#define G_STAGE   (2*G_A_BYTES + 2*G_B_BYTES)
#define G_SMEM    (2*G_STAGE)

#define OFF_AH(s) ((s)*G_STAGE)
#define OFF_AL(s) ((s)*G_STAGE + G_A_BYTES)
#define OFF_BH(s) ((s)*G_STAGE + 2*G_A_BYTES)
#define OFF_BL(s) ((s)*G_STAGE + 2*G_A_BYTES + G_B_BYTES)

__device__ __forceinline__ void g_load_stage(
    uint32_t sb, int s, int k0, int mbase, int nbase,
    const __nv_bfloat16* Ah, const __nv_bfloat16* Al,
    const __nv_bfloat16* Bh, const __nv_bfloat16* Bl, int tid)
{
    #pragma unroll
    for (int i = 0; i < 2; i++) {
        const int c = tid + i*512;
        const int row = c >> 2;
        const int kc  = (c & 3) * 8;
        const size_t g = (size_t)(mbase + row)*1024 + k0 + kc;
        const uint32_t d = sb + row*80 + kc*2;
        cpa16(d + OFF_AH(s), Ah + g);
        cpa16(d + OFF_AL(s), Al + g);
    }
    {
        const int row = tid >> 2;
        const int kc  = (tid & 3) * 8;
        const size_t g = (size_t)(nbase + row)*1024 + k0 + kc;
        const uint32_t d = sb + row*80 + kc*2;
        cpa16(d + OFF_BH(s), Bh + g);
        cpa16(d + OFF_BL(s), Bl + g);
    }
}

__global__ __launch_bounds__(512, 1) void gemm_mma(
    const __nv_bfloat16* __restrict__ Ah, const __nv_bfloat16* __restrict__ Al,
    const __nv_bfloat16* __restrict__ Bh, const __nv_bfloat16* __restrict__ Bl,
    const float* __restrict__ bias, float* __restrict__ C,
    __nv_bfloat16* __restrict__ Ch, __nv_bfloat16* __restrict__ Cl)
{
    extern __shared__ char smem[];
    const uint32_t sb = smem_u32(smem);
    const int tid = threadIdx.x;
    const int wid = tid >> 5;
    const int lid = tid & 31;
    const int warpM = (wid >> 2) * 64;
    const int warpN = (wid & 3) * 32;
    const int mbase = blockIdx.y * GBM;
    const int nbase = blockIdx.x * GBN;

    float acc[4][4][4];
    #pragma unroll
    for (int m = 0; m < 4; m++)
        #pragma unroll
        for (int n = 0; n < 4; n++)
            #pragma unroll
            for (int r = 0; r < 4; r++) acc[m][n][r] = 0.0f;

    const int aRow  = warpM + (lid & 15);
    const int aKoff = (lid >> 4) * 8;
    const int bRow  = warpN + (lid & 7) + (lid >> 4)*8;
    const int bKoff = ((lid >> 3) & 1) * 8;

    g_load_stage(sb, 0, 0, mbase, nbase, Ah, Al, Bh, Bl, tid);
    CP_COMMIT();
    g_load_stage(sb, 1, GBK, mbase, nbase, Ah, Al, Bh, Bl, tid);
    CP_COMMIT();

    for (int it = 0; it < 32; it++) {
        const int s = it & 1;
        CP_WAIT1();
        __syncthreads();

        const uint32_t aBase = sb + OFF_AH(s) + aRow*80 + aKoff*2;
        const uint32_t alBase= sb + OFF_AL(s) + aRow*80 + aKoff*2;
        const uint32_t bBase = sb + OFF_BH(s) + bRow*80 + bKoff*2;
        const uint32_t blBase= sb + OFF_BL(s) + bRow*80 + bKoff*2;

        #pragma unroll
        for (int kk = 0; kk < 2; kk++) {
            const uint32_t kb = kk * 32;
            uint32_t af[4][4], bh2[4][2], bl2[4][2];
            #pragma unroll
            for (int p = 0; p < 2; p++) {
                uint32_t r0,r1,r2,r3;
                ldsm_x4(r0,r1,r2,r3, bBase + p*16*80 + kb);
                bh2[p*2+0][0]=r0; bh2[p*2+0][1]=r1; bh2[p*2+1][0]=r2; bh2[p*2+1][1]=r3;
                ldsm_x4(r0,r1,r2,r3, blBase + p*16*80 + kb);
                bl2[p*2+0][0]=r0; bl2[p*2+0][1]=r1; bl2[p*2+1][0]=r2; bl2[p*2+1][1]=r3;
            }
            #pragma unroll
            for (int m = 0; m < 4; m++)
                ldsm_x4(af[m][0], af[m][1], af[m][2], af[m][3], aBase + m*16*80 + kb);
            #pragma unroll
            for (int m = 0; m < 4; m++)
                #pragma unroll
                for (int n = 0; n < 4; n++) {
                    mma16816(acc[m][n], af[m], bh2[n][0], bh2[n][1]);
                    mma16816(acc[m][n], af[m], bl2[n][0], bl2[n][1]);
                }
            #pragma unroll
            for (int m = 0; m < 4; m++)
                ldsm_x4(af[m][0], af[m][1], af[m][2], af[m][3], alBase + m*16*80 + kb);
            #pragma unroll
            for (int m = 0; m < 4; m++)
                #pragma unroll
                for (int n = 0; n < 4; n++)
                    mma16816(acc[m][n], af[m], bh2[n][0], bh2[n][1]);
        }
        __syncthreads();
        if (it + 2 < 32)
            g_load_stage(sb, s, (it + 2)*GBK, mbase, nbase, Ah, Al, Bh, Bl, tid);
        CP_COMMIT();
    }

    // Epilogue
    const int r0base = mbase + warpM + (lid >> 2);
    const int cbase  = nbase + warpN + (lid & 3)*2;
    #pragma unroll
    for (int m = 0; m < 4; m++) {
        #pragma unroll
        for (int n = 0; n < 4; n++) {
            const int cc = cbase + n*8;
            const float2 bi = *(const float2*)&bias[cc];
            const int ra = r0base + m*16;
            float v0 = acc[m][n][0] + bi.x, v1 = acc[m][n][1] + bi.y;
            float v2 = acc[m][n][2] + bi.x, v3 = acc[m][n][3] + bi.y;
            if (C) {
                *(float2*)&C[(size_t)ra*1024 + cc] = make_float2(v0, v1);
                *(float2*)&C[(size_t)(ra + 8)*1024 + cc] = make_float2(v2, v3);
            } else {
                uint32_t h01 = packbf(v0, v1);
                uint32_t l01 = packbf(v0 - __uint_as_float(h01 << 16),
                                      v1 - __uint_as_float(h01 & 0xFFFF0000u));
                uint32_t h23 = packbf(v2, v3);
                uint32_t l23 = packbf(v2 - __uint_as_float(h23 << 16),
                                      v3 - __uint_as_float(h23 & 0xFFFF0000u));
                *(uint32_t*)&Ch[(size_t)ra*1024 + cc] = h01;
                *(uint32_t*)&Cl[(size_t)ra*1024 + cc] = l01;
                *(uint32_t*)&Ch[(size_t)(ra + 8)*1024 + cc] = h23;
                *(uint32_t*)&Cl[(size_t)(ra + 8)*1024 + cc] = l23;
            }
        }
    }
}

// ---------------------------------------------------------------------------
// Flash attention (causal), mma.sync bf16 split-precision.
// 1 CTA = 128 threads (4 warps) per (b,h,64-row q tile). Warp w: rows w*16..+15.
// Smem: Qh/Ql [64x72] + 2 stages of (Kh,Kl,Vh,Vl)[64x72]; 144B rows.
// ---------------------------------------------------------------------------
#define FTILE 9216                   // 64*144 bytes
#define FSTAGE (4*FTILE)             // 36864
#define F_SMEM (2*FTILE + 2*FSTAGE)  // 92160

__global__ __launch_bounds__(128, 2) void flash_mma(
    const __nv_bfloat16* __restrict__ qh, const __nv_bfloat16* __restrict__ ql,
    const __nv_bfloat16* __restrict__ kh, const __nv_bfloat16* __restrict__ kl,
    const __nv_bfloat16* __restrict__ vh, const __nv_bfloat16* __restrict__ vl,
    __nv_bfloat16* __restrict__ oh, __nv_bfloat16* __restrict__ ol)
{
    extern __shared__ char smem[];
    const uint32_t sb = smem_u32(smem);
    const int tid = threadIdx.x;
    const int wid = tid >> 5;
    const int lid = tid & 31;
    const int qt  = (int)gridDim.x - 1 - (int)blockIdx.x;
    const int bh_ = blockIdx.y;
    const int b = bh_ >> 4;
    const int h = bh_ & 15;
    const size_t base = (size_t)b * SS * DD + (size_t)h * DK;
    const int rowg0 = qt * 64;
    const int warpRow = wid * 16;

    // Prologue: Q tile (hi+lo) + KV stage 0 -> group A; KV stage 1 -> group B
    for (int i = tid; i < 512; i += 128) {
        const int r = i >> 3, kc = (i & 7) * 8;
        const size_t g = base + (size_t)(rowg0 + r)*DD + kc;
        const uint32_t d = sb + r*144 + kc*2;
        cpa16(d, qh + g);
        cpa16(d + FTILE, ql + g);
    }
    {
        const uint32_t st = sb + 2*FTILE;
        for (int i = tid; i < 512; i += 128) {
            const int r = i >> 3, kc = (i & 7) * 8;
            const size_t g = base + (size_t)(r)*DD + kc;
            const uint32_t d = st + r*144 + kc*2;
            cpa16(d,           kh + g);
            cpa16(d + FTILE,   kl + g);
            cpa16(d + 2*FTILE, vh + g);
            cpa16(d + 3*FTILE, vl + g);
        }
    }
    CP_COMMIT();
    if (qt >= 1) {
        const uint32_t st = sb + 2*FTILE + FSTAGE;
        for (int i = tid; i < 512; i += 128) {
            const int r = i >> 3, kc = (i & 7) * 8;
            const size_t g = base + (size_t)(64 + r)*DD + kc;
            const uint32_t d = st + r*144 + kc*2;
            cpa16(d,           kh + g);
            cpa16(d + FTILE,   kl + g);
            cpa16(d + 2*FTILE, vh + g);
            cpa16(d + 3*FTILE, vl + g);
        }
    }
    CP_COMMIT();

    float oacc[8][4];
    #pragma unroll
    for (int t = 0; t < 8; t++)
        #pragma unroll
        for (int r = 0; r < 4; r++) oacc[t][r] = 0.0f;
    float m0 = -1.0e30f, m1 = -1.0e30f, l0 = 0.0f, l1 = 0.0f;

    const uint32_t aAddr = sb + (warpRow + (lid & 15))*144 + ((lid >> 4)*8)*2;
    const int row0 = warpRow + (lid >> 2);
    const int row1 = row0 + 8;
    const int colB = (lid & 3) * 2;

    for (int it = 0; it <= qt; it++) {
        CP_WAIT1();
        __syncthreads();
        const uint32_t st = sb + 2*FTILE + (it & 1)*FSTAGE;

        // ---- S = Q @ K^T (split x3) ----
        float sacc[8][4];
        #pragma unroll
        for (int t = 0; t < 8; t++)
            #pragma unroll
            for (int r = 0; r < 4; r++) sacc[t][r] = 0.0f;

        #pragma unroll
        for (int kk = 0; kk < 4; kk++) {
            uint32_t ah4[4], al4[4];
            ldsm_x4(ah4[0], ah4[1], ah4[2], ah4[3], aAddr + kk*32);
            ldsm_x4(al4[0], al4[1], al4[2], al4[3], aAddr + FTILE + kk*32);
            const uint32_t kbase = st + ((lid & 7) + (lid >> 4)*8)*144
                                 + (((lid >> 3) & 1)*8 + kk*16)*2;
            #pragma unroll
            for (int p = 0; p < 4; p++) {
                uint32_t h0,h1,h2,h3, x0,x1,x2,x3;
                ldsm_x4(h0,h1,h2,h3, kbase + p*16*144);
                ldsm_x4(x0,x1,x2,x3, kbase + FTILE + p*16*144);
                mma16816(sacc[2*p],   ah4, h0, h1);
                mma16816(sacc[2*p],   ah4, x0, x1);
                mma16816(sacc[2*p],   al4, h0, h1);
                mma16816(sacc[2*p+1], ah4, h2, h3);
                mma16816(sacc[2*p+1], ah4, x2, x3);
                mma16816(sacc[2*p+1], al4, h2, h3);
            }
        }

        // ---- scale + causal mask ----
        #pragma unroll
        for (int t = 0; t < 8; t++)
            #pragma unroll
            for (int r = 0; r < 4; r++) sacc[t][r] *= 0.125f;
        if (it == qt) {
            #pragma unroll
            for (int t = 0; t < 8; t++) {
                const int c0 = t*8 + colB;
                if (c0     > row0) sacc[t][0] = -1.0e30f;
                if (c0 + 1 > row0) sacc[t][1] = -1.0e30f;
                if (c0     > row1) sacc[t][2] = -1.0e30f;
                if (c0 + 1 > row1) sacc[t][3] = -1.0e30f;
            }
        }

        // ---- streaming softmax (rows row0, row1; 4 lanes/row) ----
        float rm0 = -1.0e30f, rm1 = -1.0e30f;
        #pragma unroll
        for (int t = 0; t < 8; t++) {
            rm0 = fmaxf(rm0, fmaxf(sacc[t][0], sacc[t][1]));
            rm1 = fmaxf(rm1, fmaxf(sacc[t][2], sacc[t][3]));
        }
        rm0 = fmaxf(rm0, __shfl_xor_sync(0xffffffffu, rm0, 1, 4));
        rm0 = fmaxf(rm0, __shfl_xor_sync(0xffffffffu, rm0, 2, 4));
        rm1 = fmaxf(rm1, __shfl_xor_sync(0xffffffffu, rm1, 1, 4));
        rm1 = fmaxf(rm1, __shfl_xor_sync(0xffffffffu, rm1, 2, 4));
        const float mn0 = fmaxf(m0, rm0), mn1 = fmaxf(m1, rm1);
        const float f0 = __expf(m0 - mn0), f1 = __expf(m1 - mn1);
        m0 = mn0; m1 = mn1;
        float s0 = 0.0f, s1 = 0.0f;
        #pragma unroll
        for (int t = 0; t < 8; t++) {
            float p0 = __expf(sacc[t][0] - mn0);
            float p1 = __expf(sacc[t][1] - mn0);
            float p2 = __expf(sacc[t][2] - mn1);
            float p3 = __expf(sacc[t][3] - mn1);
            sacc[t][0] = p0; sacc[t][1] = p1; sacc[t][2] = p2; sacc[t][3] = p3;
            s0 += p0 + p1; s1 += p2 + p3;
        }
        s0 += __shfl_xor_sync(0xffffffffu, s0, 1, 4);
        s0 += __shfl_xor_sync(0xffffffffu, s0, 2, 4);
        s1 += __shfl_xor_sync(0xffffffffu, s1, 1, 4);
        s1 += __shfl_xor_sync(0xffffffffu, s1, 2, 4);
        l0 = l0*f0 + s0;
        l1 = l1*f1 + s1;
        #pragma unroll
        for (int t = 0; t < 8; t++) {
            oacc[t][0] *= f0; oacc[t][1] *= f0;
            oacc[t][2] *= f1; oacc[t][3] *= f1;
        }

        // ---- O += P @ V (split x3); P frags built from registers ----
        #pragma unroll
        for (int kk = 0; kk < 4; kk++) {
            uint32_t ph4[4], pl4[4];
            #pragma unroll
            for (int u = 0; u < 2; u++) {           // u=0: sacc[2kk] (k lo), u=1: k hi
                const int t = 2*kk + u;
                uint32_t hA = packbf(sacc[t][0], sacc[t][1]);
                uint32_t hB = packbf(sacc[t][2], sacc[t][3]);
                ph4[2*u+0] = hA; ph4[2*u+1] = hB;
                pl4[2*u+0] = packbf(sacc[t][0] - __uint_as_float(hA << 16),
                                    sacc[t][1] - __uint_as_float(hA & 0xFFFF0000u));
                pl4[2*u+1] = packbf(sacc[t][2] - __uint_as_float(hB << 16),
                                    sacc[t][3] - __uint_as_float(hB & 0xFFFF0000u));
            }
            const uint32_t vbase = st + 2*FTILE
                + (kk*16 + (lid & 7) + ((lid >> 3) & 1)*8)*144 + ((lid >> 4)*8)*2;
            #pragma unroll
            for (int p = 0; p < 4; p++) {
                uint32_t h0,h1,h2,h3, x0,x1,x2,x3;
                ldsm_x4t(h0,h1,h2,h3, vbase + p*32);
                ldsm_x4t(x0,x1,x2,x3, vbase + FTILE + p*32);
                mma16816(oacc[2*p],   ph4, h0, h1);
                mma16816(oacc[2*p],   ph4, x0, x1);
                mma16816(oacc[2*p],   pl4, h0, h1);
                mma16816(oacc[2*p+1], ph4, h2, h3);
                mma16816(oacc[2*p+1], ph4, x2, x3);
                mma16816(oacc[2*p+1], pl4, h2, h3);
            }
        }

        __syncthreads();
        if (it + 2 <= qt) {
            const uint32_t stn = sb + 2*FTILE + (it & 1)*FSTAGE;
            for (int i = tid; i < 512; i += 128) {
                const int r = i >> 3, kc = (i & 7) * 8;
                const size_t g = base + (size_t)((it + 2)*64 + r)*DD + kc;
                const uint32_t d = stn + r*144 + kc*2;
                cpa16(d,           kh + g);
                cpa16(d + FTILE,   kl + g);
                cpa16(d + 2*FTILE, vh + g);
                cpa16(d + 3*FTILE, vl + g);
            }
        }
        CP_COMMIT();
    }

    // ---- epilogue: normalize, split to bf16 hi/lo, store ----
    const float il0 = 1.0f / l0, il1 = 1.0f / l1;
    const size_t ga0 = base + (size_t)(rowg0 + row0)*DD + colB;
    const size_t ga1 = base + (size_t)(rowg0 + row1)*DD + colB;
    #pragma unroll
    for (int t = 0; t < 8; t++) {
        const float v0 = oacc[t][0]*il0, v1 = oacc[t][1]*il0;
        const float v2 = oacc[t][2]*il1, v3 = oacc[t][3]*il1;
        uint32_t h01 = packbf(v0, v1);
        uint32_t l01 = packbf(v0 - __uint_as_float(h01 << 16),
                              v1 - __uint_as_float(h01 & 0xFFFF0000u));
        uint32_t h23 = packbf(v2, v3);
        uint32_t l23 = packbf(v2 - __uint_as_float(h23 << 16),
                              v3 - __uint_as_float(h23 & 0xFFFF0000u));
        *(uint32_t*)&oh[ga0 + t*8] = h01;
        *(uint32_t*)&ol[ga0 + t*8] = l01;
        *(uint32_t*)&oh[ga1 + t*8] = h23;
        *(uint32_t*)&ol[ga1 + t*8] = l23;
    }
}

// ---------------------------------------------------------------------------
// Launch
// ---------------------------------------------------------------------------
extern "C" void kernel_launch(void* const* d_in, const int* in_sizes, int n_in,
                              void* d_out, int out_size)
{
    const float* Q   = (const float*)d_in[0];
    const float* K   = (const float*)d_in[1];
    const float* V   = (const float*)d_in[2];
    const float* W_q = (const float*)d_in[3];
    const float* b_q = (const float*)d_in[4];
    const float* W_k = (const float*)d_in[5];
    const float* b_k = (const float*)d_in[6];
    const float* W_v = (const float*)d_in[7];
    const float* b_v = (const float*)d_in[8];
    const float* W_o = (const float*)d_in[9];
    const float* b_o = (const float*)d_in[10];
    float* out = (float*)d_out;

    __nv_bfloat16 *xh, *xl, *qh, *ql, *kh, *kl, *vh, *vl, *oh, *ol, *bh, *bl;
    cudaGetSymbolAddress((void**)&xh, g_xh);
    cudaGetSymbolAddress((void**)&xl, g_xl);
    cudaGetSymbolAddress((void**)&qh, g_qh);
    cudaGetSymbolAddress((void**)&ql, g_ql);
    cudaGetSymbolAddress((void**)&kh, g_kh);
    cudaGetSymbolAddress((void**)&kl, g_kl);
    cudaGetSymbolAddress((void**)&vh, g_vh);
    cudaGetSymbolAddress((void**)&vl, g_vl);
    cudaGetSymbolAddress((void**)&oh, g_oh);
    cudaGetSymbolAddress((void**)&ol, g_ol);
    cudaGetSymbolAddress((void**)&bh, g_bh);
    cudaGetSymbolAddress((void**)&bl, g_bl);

    cudaFuncSetAttribute(gemm_mma, cudaFuncAttributeMaxDynamicSharedMemorySize, G_SMEM);
    cudaFuncSetAttribute(flash_mma, cudaFuncAttributeMaxDynamicSharedMemorySize, F_SMEM);

    const int caGrid = (MROWS*DD) / (256*8);   // 2048
    dim3 cwGrid(16, 16);
    dim3 gGrid(DD/GBN, MROWS/GBM);             // (8, 16) = 128 CTAs

    conv_act<<<caGrid, 256>>>(Q, xh, xl);
    conv_w  <<<cwGrid, 256>>>(W_q, bh, bl);
    gemm_mma<<<gGrid, 512, G_SMEM>>>(xh, xl, bh, bl, b_q, nullptr, qh, ql);

    conv_act<<<caGrid, 256>>>(K, xh, xl);
    conv_w  <<<cwGrid, 256>>>(W_k, bh, bl);
    gemm_mma<<<gGrid, 512, G_SMEM>>>(xh, xl, bh, bl, b_k, nullptr, kh, kl);

    conv_act<<<caGrid, 256>>>(V, xh, xl);
    conv_w  <<<cwGrid, 256>>>(W_v, bh, bl);
    gemm_mma<<<gGrid, 512, G_SMEM>>>(xh, xl, bh, bl, b_v, nullptr, vh, vl);

    dim3 fGrid(SS/64, BB*HH);                  // (32, 32)
    flash_mma<<<fGrid, 128, F_SMEM>>>(qh, ql, kh, kl, vh, vl, oh, ol);

    conv_w  <<<cwGrid, 256>>>(W_o, bh, bl);
    gemm_mma<<<gGrid, 512, G_SMEM>>>(oh, ol, bh, bl, b_o, out, nullptr, nullptr);
}